// round 8
// baseline (speedup 1.0000x reference)
#include <cuda_runtime.h>
#include <math.h>
#include <stdint.h>

// ---------------------------------------------------------------------------
// Problem constants (fixed shapes for SVTRBlock_43087111914328)
// ---------------------------------------------------------------------------
#define B_    8
#define SEQ   1024
#define DIM   768
#define NHEAD 12
#define HD    64
#define TD    2304          // 3*DIM
#define HMLP  3072          // 4*DIM
#define ROWS  (B_*SEQ)      // 8192

// ---------------------------------------------------------------------------
// Scratch (device globals; no allocation allowed in kernel_launch)
// ---------------------------------------------------------------------------
__device__ float g_qkv[B_ * SEQ * TD];                       //  75.5 MB
__device__ float g_attn[ROWS * DIM];                         //  25.2 MB
__device__ float g_x1[ROWS * DIM];                           //  25.2 MB
__device__ float g_y[ROWS * DIM];                            //  25.2 MB
__device__ float g_h[ROWS * HMLP];                           // 100.7 MB

// ---------------------------------------------------------------------------
// Helpers
// ---------------------------------------------------------------------------
static __device__ __forceinline__ uint32_t smem_u32(const void* p) {
    return (uint32_t)__cvta_generic_to_shared(p);
}
static __device__ __forceinline__ uint32_t f2tf(float f) {
    uint32_t r;
    asm("cvt.rna.tf32.f32 %0, %1;" : "=r"(r) : "f"(f));
    return r;
}
static __device__ __forceinline__ void mma_tf32(float c[4],
                                                uint32_t a0, uint32_t a1, uint32_t a2, uint32_t a3,
                                                uint32_t b0, uint32_t b1) {
    asm volatile(
        "mma.sync.aligned.m16n8k8.row.col.f32.tf32.tf32.f32 "
        "{%0,%1,%2,%3}, {%4,%5,%6,%7}, {%8,%9}, {%0,%1,%2,%3};"
        : "+f"(c[0]), "+f"(c[1]), "+f"(c[2]), "+f"(c[3])
        : "r"(a0), "r"(a1), "r"(a2), "r"(a3), "r"(b0), "r"(b1));
}
#define CP_ASYNC16(dst, src) \
    asm volatile("cp.async.cg.shared.global [%0], [%1], 16;" :: "r"(dst), "l"(src))
#define CP_COMMIT()  asm volatile("cp.async.commit_group;")
#define CP_WAIT_1()  asm volatile("cp.async.wait_group 1;")
#define CP_WAIT_0()  asm volatile("cp.async.wait_group 0;")

// ---------------------------------------------------------------------------
// TF32 tensor-core GEMM, 3-stage cp.async pipeline, fused epilogues.
// Tile buffers live in DYNAMIC smem (static limit is 48KB; 3 stages need 56KB).
// ---------------------------------------------------------------------------
enum { EPI_NONE = 0, EPI_BIAS = 1, EPI_BIAS_GELU = 2, EPI_BIAS_RES = 3, EPI_SCALE = 4 };

template <int BM, int BN, bool BT>
struct GemmSmem {
    static constexpr int BK  = 16;
    static constexpr int STG = 3;
    static constexpr int APAD = 20;
    static constexpr int B_ROWS   = BT ? BN : BK;
    static constexpr int B_STRIDE = BT ? APAD : (BN + 4);
    static constexpr int A_FLOATS = STG * BM * APAD;
    static constexpr int B_FLOATS = STG * B_ROWS * B_STRIDE;
    static constexpr int BYTES = (A_FLOATS + B_FLOATS) * 4;
};

template <int BM, int BN, int WARPS_M, int WARPS_N, bool BT, int EPI>
__global__ void __launch_bounds__(256)
mma_gemm(const float* __restrict__ A, int lda, long sAb, long sAh,
         const float* __restrict__ Bp, int ldb, long sBb, long sBh,
         float* __restrict__ C, int ldc, long sCb, long sCh,
         const float* __restrict__ bias,
         const float* __restrict__ res, int ldres,
         int K, int nh, float scale)
{
    static_assert(WARPS_M * WARPS_N == 8, "256 threads");
    using SM = GemmSmem<BM, BN, BT>;
    constexpr int BK  = SM::BK;
    constexpr int STG = SM::STG;
    constexpr int WM  = BM / WARPS_M;
    constexpr int WN  = BN / WARPS_N;
    constexpr int MT  = WM / 16;
    constexpr int NT_ = WN / 8;
    constexpr int APAD = SM::APAD;
    constexpr int B_STRIDE = SM::B_STRIDE;

    extern __shared__ float dynsm[];
    float* Asf = dynsm;                              // [STG][BM][APAD]
    float* Bsf = dynsm + SM::A_FLOATS;               // [STG][B_ROWS][B_STRIDE]
#define AS(s, r, c) Asf[((s) * BM + (r)) * APAD + (c)]
#define BS(s, r, c) Bsf[((s) * SM::B_ROWS + (r)) * B_STRIDE + (c)]

    const int tid  = threadIdx.x;
    const int warp = tid >> 5;
    const int lane = tid & 31;
    const int gid  = lane >> 2;
    const int tig  = lane & 3;
    const int wm   = (warp / WARPS_N) * WM;
    const int wn   = (warp % WARPS_N) * WN;

    const int z  = blockIdx.z;
    const int zb = z / nh;
    const int zh = z - zb * nh;
    A  += (size_t)zb * sAb + (size_t)zh * sAh;
    Bp += (size_t)zb * sBb + (size_t)zh * sBh;
    C  += (size_t)zb * sCb + (size_t)zh * sCh;

    const int rowBase = blockIdx.y * BM;
    const int colBase = blockIdx.x * BN;

    float acc[MT][NT_][4];
#pragma unroll
    for (int i = 0; i < MT; i++)
#pragma unroll
        for (int j = 0; j < NT_; j++)
#pragma unroll
            for (int r = 0; r < 4; r++) acc[i][j][r] = 0.0f;

    auto load_tile = [&](int st, int k0) {
        constexpr int AV = BM * 4;
#pragma unroll
        for (int i = tid; i < AV; i += 256) {
            int row = i >> 2, c = (i & 3) << 2;
            CP_ASYNC16(smem_u32(&AS(st, row, c)),
                       &A[(size_t)(rowBase + row) * lda + k0 + c]);
        }
        if (BT) {
            constexpr int BV = BN * 4;
#pragma unroll
            for (int i = tid; i < BV; i += 256) {
                int row = i >> 2, c = (i & 3) << 2;
                CP_ASYNC16(smem_u32(&BS(st, row, c)),
                           &Bp[(size_t)(colBase + row) * ldb + k0 + c]);
            }
        } else {
            constexpr int BV = BK * (BN / 4);
#pragma unroll
            for (int i = tid; i < BV; i += 256) {
                int kk = i / (BN / 4), c = (i % (BN / 4)) << 2;
                CP_ASYNC16(smem_u32(&BS(st, kk, c)),
                           &Bp[(size_t)(k0 + kk) * ldb + colBase + c]);
            }
        }
    };

    const int nTiles = K / BK;          // >= 3 for all call sites
    load_tile(0, 0);
    CP_COMMIT();
    load_tile(1, BK);
    CP_COMMIT();

    for (int t = 0; t < nTiles; t++) {
        const int st = t % STG;
        if (t + 1 < nTiles) CP_WAIT_1(); else CP_WAIT_0();
        __syncthreads();                 // tile t visible; buffer (t+2)%STG free
        if (t + 2 < nTiles) {
            load_tile((t + 2) % STG, (t + 2) * BK);
            CP_COMMIT();
        }

#pragma unroll
        for (int kb = 0; kb < BK; kb += 8) {
            uint32_t af[MT][4];
#pragma unroll
            for (int mt = 0; mt < MT; mt++) {
                const int m0 = wm + mt * 16;
                af[mt][0] = f2tf(AS(st, m0 + gid,     kb + tig    ));
                af[mt][1] = f2tf(AS(st, m0 + gid + 8, kb + tig    ));
                af[mt][2] = f2tf(AS(st, m0 + gid,     kb + tig + 4));
                af[mt][3] = f2tf(AS(st, m0 + gid + 8, kb + tig + 4));
            }
            uint32_t bf[NT_][2];
#pragma unroll
            for (int nt = 0; nt < NT_; nt++) {
                const int n0 = wn + nt * 8;
                if (BT) {
                    bf[nt][0] = f2tf(BS(st, n0 + gid, kb + tig    ));
                    bf[nt][1] = f2tf(BS(st, n0 + gid, kb + tig + 4));
                } else {
                    bf[nt][0] = f2tf(BS(st, kb + tig,     n0 + gid));
                    bf[nt][1] = f2tf(BS(st, kb + tig + 4, n0 + gid));
                }
            }
#pragma unroll
            for (int mt = 0; mt < MT; mt++)
#pragma unroll
                for (int nt = 0; nt < NT_; nt++)
                    mma_tf32(acc[mt][nt], af[mt][0], af[mt][1], af[mt][2], af[mt][3],
                             bf[nt][0], bf[nt][1]);
        }
    }
#undef AS
#undef BS

#pragma unroll
    for (int mt = 0; mt < MT; mt++) {
        const int row0 = rowBase + wm + mt * 16 + gid;
        const int row1 = row0 + 8;
#pragma unroll
        for (int nt = 0; nt < NT_; nt++) {
            const int col = colBase + wn + nt * 8 + 2 * tig;
            float v0 = acc[mt][nt][0], v1 = acc[mt][nt][1];
            float v2 = acc[mt][nt][2], v3 = acc[mt][nt][3];
            if (EPI == EPI_SCALE) { v0 *= scale; v1 *= scale; v2 *= scale; v3 *= scale; }
            if (EPI == EPI_BIAS || EPI == EPI_BIAS_GELU || EPI == EPI_BIAS_RES) {
                const float b0 = bias[col], b1 = bias[col + 1];
                v0 += b0; v1 += b1; v2 += b0; v3 += b1;
            }
            if (EPI == EPI_BIAS_GELU) {
                v0 = 0.5f * v0 * (1.0f + erff(v0 * 0.70710678118654752f));
                v1 = 0.5f * v1 * (1.0f + erff(v1 * 0.70710678118654752f));
                v2 = 0.5f * v2 * (1.0f + erff(v2 * 0.70710678118654752f));
                v3 = 0.5f * v3 * (1.0f + erff(v3 * 0.70710678118654752f));
            }
            if (EPI == EPI_BIAS_RES) {
                const float2 r0 = *(const float2*)&res[(size_t)row0 * ldres + col];
                const float2 r1 = *(const float2*)&res[(size_t)row1 * ldres + col];
                v0 += r0.x; v1 += r0.y; v2 += r1.x; v3 += r1.y;
            }
            *(float2*)&C[(size_t)row0 * ldc + col] = make_float2(v0, v1);
            *(float2*)&C[(size_t)row1 * ldc + col] = make_float2(v2, v3);
        }
    }
}

// ---------------------------------------------------------------------------
// Fused flash attention (TF32 mma, online softmax, S never leaves the SM).
// Grid: (8 q-tiles, 96 bh). 256 threads = 8 warps; warp w owns S rows 16w..16w+15.
// K/V tiles are pre-converted to TF32 IN SMEM once per CTA (kills the 8x
// redundant per-warp cvt traffic); mma operands then use raw bit loads.
// ---------------------------------------------------------------------------
#define FA_PAD 68
#define FA_QOFF 0
#define FA_KOFF (128 * FA_PAD)
#define FA_VOFF (FA_KOFF + 2 * 128 * FA_PAD)
#define FA_SMEM ((FA_VOFF + 2 * 128 * FA_PAD) * 4)

__global__ void __launch_bounds__(256, 1)
flash_attn(const float* __restrict__ qkv, float* __restrict__ attn)
{
    extern __shared__ float sm[];
    float* Qs = sm + FA_QOFF;
    float* Ks = sm + FA_KOFF;   // [2][128][FA_PAD]
    float* Vs = sm + FA_VOFF;

    const int tid  = threadIdx.x;
    const int warp = tid >> 5;
    const int lane = tid & 31;
    const int gid  = lane >> 2;
    const int tig  = lane & 3;

    const int bh = blockIdx.y;
    const int b  = bh / NHEAD;
    const int h  = bh - b * NHEAD;
    const float* qp = qkv + (size_t)b * SEQ * TD + h * HD;
    const float* kp = qp + DIM;
    const float* vp = qp + 2 * DIM;
    const int q0 = blockIdx.x * 128;

    // ---- load Q tile + prefetch K0/V0 (one commit group)
#pragma unroll
    for (int i = tid; i < 128 * 16; i += 256) {
        int row = i >> 4, c = (i & 15) << 2;
        CP_ASYNC16(smem_u32(&Qs[row * FA_PAD + c]), &qp[(size_t)(q0 + row) * TD + c]);
    }
#pragma unroll
    for (int i = tid; i < 128 * 16; i += 256) {
        int row = i >> 4, c = (i & 15) << 2;
        CP_ASYNC16(smem_u32(&Ks[row * FA_PAD + c]), &kp[(size_t)row * TD + c]);
        CP_ASYNC16(smem_u32(&Vs[row * FA_PAD + c]), &vp[(size_t)row * TD + c]);
    }
    CP_COMMIT();

    uint32_t qf[8][4];                  // Q fragments, converted once
    float oacc[8][4];
#pragma unroll
    for (int i = 0; i < 8; i++)
#pragma unroll
        for (int r = 0; r < 4; r++) oacc[i][r] = 0.0f;
    float m0 = -1e30f, m1 = -1e30f, l0 = 0.0f, l1 = 0.0f;

    const int r0s = 16 * warp + gid;    // smem row (lo)
    for (int t = 0; t < 8; t++) {
        const int st = t & 1;
        if (t < 7) {
            const int nb = (t + 1) & 1;
            const float* kn = kp + (size_t)(t + 1) * 128 * TD;
            const float* vn = vp + (size_t)(t + 1) * 128 * TD;
#pragma unroll
            for (int i = tid; i < 128 * 16; i += 256) {
                int row = i >> 4, c = (i & 15) << 2;
                CP_ASYNC16(smem_u32(&Ks[(nb * 128 + row) * FA_PAD + c]), &kn[(size_t)row * TD + c]);
                CP_ASYNC16(smem_u32(&Vs[(nb * 128 + row) * FA_PAD + c]), &vn[(size_t)row * TD + c]);
            }
            CP_COMMIT();
            CP_WAIT_1();
        } else {
            CP_WAIT_0();
        }
        __syncthreads();

        // ---- pre-convert K/V tile (stage st) to TF32 in place, once per CTA
        {
            float* Kb = Ks + st * 128 * FA_PAD;
            float* Vb = Vs + st * 128 * FA_PAD;
#pragma unroll
            for (int i = tid; i < 128 * 4; i += 256) {
                int row = i >> 2, c = (i & 3) << 4;     // 4 x float4 groups of 16
#pragma unroll
                for (int cc = 0; cc < 4; cc++) {
                    float4* pk = (float4*)&Kb[row * FA_PAD + c + 4 * cc];
                    float4 v = *pk;
                    uint4 u = make_uint4(f2tf(v.x), f2tf(v.y), f2tf(v.z), f2tf(v.w));
                    *(uint4*)pk = u;
                    float4* pv = (float4*)&Vb[row * FA_PAD + c + 4 * cc];
                    v = *pv;
                    u = make_uint4(f2tf(v.x), f2tf(v.y), f2tf(v.z), f2tf(v.w));
                    *(uint4*)pv = u;
                }
            }
        }
        __syncthreads();

        if (t == 0) {
#pragma unroll
            for (int kb = 0; kb < 8; kb++) {
                qf[kb][0] = f2tf(Qs[(r0s    ) * FA_PAD + kb * 8 + tig    ]);
                qf[kb][1] = f2tf(Qs[(r0s + 8) * FA_PAD + kb * 8 + tig    ]);
                qf[kb][2] = f2tf(Qs[(r0s    ) * FA_PAD + kb * 8 + tig + 4]);
                qf[kb][3] = f2tf(Qs[(r0s + 8) * FA_PAD + kb * 8 + tig + 4]);
            }
        }

        // ---- S = Q @ K^T  (16 rows x 128 cols per warp); K already TF32 bits
        float sacc[16][4];
#pragma unroll
        for (int i = 0; i < 16; i++)
#pragma unroll
            for (int r = 0; r < 4; r++) sacc[i][r] = 0.0f;

        const float* Kb = Ks + st * 128 * FA_PAD;
#pragma unroll
        for (int kb = 0; kb < 8; kb++) {
#pragma unroll
            for (int nt = 0; nt < 16; nt++) {
                uint32_t b0 = __float_as_uint(Kb[(nt * 8 + gid) * FA_PAD + kb * 8 + tig    ]);
                uint32_t b1 = __float_as_uint(Kb[(nt * 8 + gid) * FA_PAD + kb * 8 + tig + 4]);
                mma_tf32(sacc[nt], qf[kb][0], qf[kb][1], qf[kb][2], qf[kb][3], b0, b1);
            }
        }

        // ---- online softmax (rows gid / gid+8; stats live within the quad)
        float mx0 = -1e30f, mx1 = -1e30f;
#pragma unroll
        for (int nt = 0; nt < 16; nt++) {
            sacc[nt][0] *= 0.125f; sacc[nt][1] *= 0.125f;
            sacc[nt][2] *= 0.125f; sacc[nt][3] *= 0.125f;
            mx0 = fmaxf(mx0, fmaxf(sacc[nt][0], sacc[nt][1]));
            mx1 = fmaxf(mx1, fmaxf(sacc[nt][2], sacc[nt][3]));
        }
        mx0 = fmaxf(mx0, __shfl_xor_sync(0xffffffffu, mx0, 1));
        mx0 = fmaxf(mx0, __shfl_xor_sync(0xffffffffu, mx0, 2));
        mx1 = fmaxf(mx1, __shfl_xor_sync(0xffffffffu, mx1, 1));
        mx1 = fmaxf(mx1, __shfl_xor_sync(0xffffffffu, mx1, 2));

        const float mn0 = fmaxf(m0, mx0), mn1 = fmaxf(m1, mx1);
        const float f0 = __expf(m0 - mn0), f1 = __expf(m1 - mn1);
        m0 = mn0; m1 = mn1;
        l0 *= f0;  l1 *= f1;
#pragma unroll
        for (int nd = 0; nd < 8; nd++) {
            oacc[nd][0] *= f0; oacc[nd][1] *= f0;
            oacc[nd][2] *= f1; oacc[nd][3] *= f1;
        }
#pragma unroll
        for (int nt = 0; nt < 16; nt++) {
            sacc[nt][0] = __expf(sacc[nt][0] - m0);
            sacc[nt][1] = __expf(sacc[nt][1] - m0);
            sacc[nt][2] = __expf(sacc[nt][2] - m1);
            sacc[nt][3] = __expf(sacc[nt][3] - m1);
            l0 += sacc[nt][0] + sacc[nt][1];
            l1 += sacc[nt][2] + sacc[nt][3];
        }

        // ---- O += P @ V  (A-frags from sacc via width-4 shuffles; V pre-TF32)
        const float* Vb = Vs + st * 128 * FA_PAD;
        const int s1 = tig >> 1, s2 = s1 + 2;
        const bool odd = (tig & 1);
#pragma unroll
        for (int kk = 0; kk < 16; kk++) {
            float v00 = __shfl_sync(0xffffffffu, sacc[kk][0], s1, 4);
            float v01 = __shfl_sync(0xffffffffu, sacc[kk][1], s1, 4);
            float v02 = __shfl_sync(0xffffffffu, sacc[kk][0], s2, 4);
            float v03 = __shfl_sync(0xffffffffu, sacc[kk][1], s2, 4);
            float v10 = __shfl_sync(0xffffffffu, sacc[kk][2], s1, 4);
            float v11 = __shfl_sync(0xffffffffu, sacc[kk][3], s1, 4);
            float v12 = __shfl_sync(0xffffffffu, sacc[kk][2], s2, 4);
            float v13 = __shfl_sync(0xffffffffu, sacc[kk][3], s2, 4);
            uint32_t a0 = f2tf(odd ? v01 : v00);
            uint32_t a2 = f2tf(odd ? v03 : v02);
            uint32_t a1 = f2tf(odd ? v11 : v10);
            uint32_t a3 = f2tf(odd ? v13 : v12);
#pragma unroll
            for (int nd = 0; nd < 8; nd++) {
                uint32_t b0 = __float_as_uint(Vb[(kk * 8 + tig    ) * FA_PAD + nd * 8 + gid]);
                uint32_t b1 = __float_as_uint(Vb[(kk * 8 + tig + 4) * FA_PAD + nd * 8 + gid]);
                mma_tf32(oacc[nd], a0, a1, a2, a3, b0, b1);
            }
        }
        __syncthreads();
    }

    // ---- normalize and store (head-interleaved into attn [B,N,D])
    l0 += __shfl_xor_sync(0xffffffffu, l0, 1);
    l0 += __shfl_xor_sync(0xffffffffu, l0, 2);
    l1 += __shfl_xor_sync(0xffffffffu, l1, 1);
    l1 += __shfl_xor_sync(0xffffffffu, l1, 2);
    const float inv0 = 1.0f / l0, inv1 = 1.0f / l1;

    const size_t grow0 = (size_t)b * SEQ + q0 + 16 * warp + gid;
#pragma unroll
    for (int nd = 0; nd < 8; nd++) {
        const int col = h * HD + nd * 8 + 2 * tig;
        *(float2*)&attn[grow0 * DIM + col] =
            make_float2(oacc[nd][0] * inv0, oacc[nd][1] * inv0);
        *(float2*)&attn[(grow0 + 8) * DIM + col] =
            make_float2(oacc[nd][2] * inv1, oacc[nd][3] * inv1);
    }
}

// ---------------------------------------------------------------------------
// LayerNorm over 768 columns (one block = one row, 256 threads x 3 elems)
// ---------------------------------------------------------------------------
__global__ void layernorm_768(const float* __restrict__ in, float* __restrict__ out,
                              const float* __restrict__ g, const float* __restrict__ bb)
{
    __shared__ float sm[33];
    const size_t row = blockIdx.x;
    const float* p = in + row * DIM;
    const int t = threadIdx.x;
    const float x0 = p[t], x1 = p[t + 256], x2 = p[t + 512];

    float s = x0 + x1 + x2;
#pragma unroll
    for (int o = 16; o; o >>= 1) s += __shfl_xor_sync(0xffffffffu, s, o);
    const int w = t >> 5, l = t & 31;
    if (l == 0) sm[w] = s;
    __syncthreads();
    if (t == 0) {
        float r = 0.0f;
#pragma unroll
        for (int i = 0; i < 8; i++) r += sm[i];
        sm[32] = r;
    }
    __syncthreads();
    const float mu = sm[32] * (1.0f / DIM);

    const float d0 = x0 - mu, d1 = x1 - mu, d2 = x2 - mu;
    float q = d0 * d0 + d1 * d1 + d2 * d2;
#pragma unroll
    for (int o = 16; o; o >>= 1) q += __shfl_xor_sync(0xffffffffu, q, o);
    __syncthreads();
    if (l == 0) sm[w] = q;
    __syncthreads();
    if (t == 0) {
        float r = 0.0f;
#pragma unroll
        for (int i = 0; i < 8; i++) r += sm[i];
        sm[32] = r;
    }
    __syncthreads();
    const float var = sm[32] * (1.0f / DIM);
    const float inv = rsqrtf(var + 1e-6f);

    float* o = out + row * DIM;
    o[t]       = d0 * inv * g[t]       + bb[t];
    o[t + 256] = d1 * inv * g[t + 256] + bb[t + 256];
    o[t + 512] = d2 * inv * g[t + 512] + bb[t + 512];
}

// ---------------------------------------------------------------------------
// Launch
// ---------------------------------------------------------------------------
extern "C" void kernel_launch(void* const* d_in, const int* in_sizes, int n_in,
                              void* d_out, int out_size)
{
    const float* x      = (const float*)d_in[0];
    const float* qkv_w  = (const float*)d_in[1];
    const float* qkv_b  = (const float*)d_in[2];
    const float* proj_w = (const float*)d_in[3];
    const float* proj_b = (const float*)d_in[4];
    const float* ln1_g  = (const float*)d_in[5];
    const float* ln1_b  = (const float*)d_in[6];
    const float* ln2_g  = (const float*)d_in[7];
    const float* ln2_b  = (const float*)d_in[8];
    const float* fc1_w  = (const float*)d_in[9];
    const float* fc1_b  = (const float*)d_in[10];
    const float* fc2_w  = (const float*)d_in[11];
    const float* fc2_b  = (const float*)d_in[12];
    float* out = (float*)d_out;

    float *qkv, *attn, *x1, *y, *h;
    cudaGetSymbolAddress((void**)&qkv,  g_qkv);
    cudaGetSymbolAddress((void**)&attn, g_attn);
    cudaGetSymbolAddress((void**)&x1,   g_x1);
    cudaGetSymbolAddress((void**)&y,    g_y);
    cudaGetSymbolAddress((void**)&h,    g_h);

    // Host-side attribute sets: immediate, idempotent, capture-safe.
    constexpr int GS = GemmSmem<128,128,false>::BYTES;   // 56,064 B
    cudaFuncSetAttribute(mma_gemm<128,128,2,4,false,EPI_BIAS>,
                         cudaFuncAttributeMaxDynamicSharedMemorySize, GS);
    cudaFuncSetAttribute(mma_gemm<128,128,2,4,false,EPI_BIAS_RES>,
                         cudaFuncAttributeMaxDynamicSharedMemorySize, GS);
    cudaFuncSetAttribute(mma_gemm<128,128,2,4,false,EPI_BIAS_GELU>,
                         cudaFuncAttributeMaxDynamicSharedMemorySize, GS);
    cudaFuncSetAttribute(flash_attn, cudaFuncAttributeMaxDynamicSharedMemorySize, FA_SMEM);

    // 1) QKV projection: [8192,768] @ [768,2304] + b -> g_qkv
    mma_gemm<128,128,2,4,false,EPI_BIAS><<<dim3(TD/128, ROWS/128, 1), 256, GS>>>(
        x, DIM, 0, 0,
        qkv_w, TD, 0, 0,
        qkv, TD, 0, 0,
        qkv_b, nullptr, 0, DIM, 1, 1.0f);

    // 2-4) Fused flash attention -> g_attn [B,N,D]
    flash_attn<<<dim3(SEQ/128, B_*NHEAD), 256, FA_SMEM>>>(qkv, attn);

    // 5) Proj + bias + residual(x) -> g_y
    mma_gemm<128,128,2,4,false,EPI_BIAS_RES><<<dim3(DIM/128, ROWS/128, 1), 256, GS>>>(
        attn, DIM, 0, 0,
        proj_w, DIM, 0, 0,
        y, DIM, 0, 0,
        proj_b, x, DIM, DIM, 1, 1.0f);

    // 6) LN1 -> g_x1
    layernorm_768<<<ROWS, 256>>>(y, x1, ln1_g, ln1_b);

    // 7) FC1 + bias + exact GELU -> g_h
    mma_gemm<128,128,2,4,false,EPI_BIAS_GELU><<<dim3(HMLP/128, ROWS/128, 1), 256, GS>>>(
        x1, DIM, 0, 0,
        fc1_w, HMLP, 0, 0,
        h, HMLP, 0, 0,
        fc1_b, nullptr, 0, DIM, 1, 1.0f);

    // 8) FC2 + bias + residual(x1) -> g_y
    mma_gemm<128,128,2,4,false,EPI_BIAS_RES><<<dim3(DIM/128, ROWS/128, 1), 256, GS>>>(
        h, HMLP, 0, 0,
        fc2_w, DIM, 0, 0,
        y, DIM, 0, 0,
        fc2_b, x1, DIM, HMLP, 1, 1.0f);

    // 9) LN2 -> out
    layernorm_768<<<ROWS, 256>>>(y, out, ln2_g, ln2_b);
}

// round 10
// speedup vs baseline: 1.0546x; 1.0546x over previous
#include <cuda_runtime.h>
#include <math.h>
#include <stdint.h>

// ---------------------------------------------------------------------------
// Problem constants (fixed shapes for SVTRBlock_43087111914328)
// ---------------------------------------------------------------------------
#define B_    8
#define SEQ   1024
#define DIM   768
#define NHEAD 12
#define HD    64
#define TD    2304          // 3*DIM
#define HMLP  3072          // 4*DIM
#define ROWS  (B_*SEQ)      // 8192

// ---------------------------------------------------------------------------
// Scratch (device globals; no allocation allowed in kernel_launch)
// ---------------------------------------------------------------------------
__device__ float g_qkv[B_ * SEQ * TD];                       //  75.5 MB (tf32-rounded)
__device__ float g_attn[ROWS * DIM];                         //  25.2 MB (tf32-rounded)
__device__ float g_x1[ROWS * DIM];                           //  25.2 MB (full fp32)
__device__ float g_x1r[ROWS * DIM];                          //  25.2 MB (tf32-rounded)
__device__ float g_y[ROWS * DIM];                            //  25.2 MB (full fp32)
__device__ float g_h[ROWS * HMLP];                           // 100.7 MB (tf32-rounded)
__device__ float g_xr[ROWS * DIM];                           //  25.2 MB (x, tf32-rounded)
// rounded weights, packed: [qkv_w | proj_w | fc1_w | fc2_w]
#define WOFF_QKV  0
#define WOFF_PROJ (DIM * TD)
#define WOFF_FC1  (WOFF_PROJ + DIM * DIM)
#define WOFF_FC2  (WOFF_FC1 + DIM * HMLP)
__device__ float g_wr[WOFF_FC2 + HMLP * DIM];                //  28.3 MB

// ---------------------------------------------------------------------------
// Helpers
// ---------------------------------------------------------------------------
static __device__ __forceinline__ uint32_t smem_u32(const void* p) {
    return (uint32_t)__cvta_generic_to_shared(p);
}
static __device__ __forceinline__ uint32_t f2tf(float f) {
    uint32_t r;
    asm("cvt.rna.tf32.f32 %0, %1;" : "=r"(r) : "f"(f));
    return r;
}
static __device__ __forceinline__ float f2tf_f(float f) {
    return __uint_as_float(f2tf(f));
}
static __device__ __forceinline__ void mma_tf32(float c[4],
                                                uint32_t a0, uint32_t a1, uint32_t a2, uint32_t a3,
                                                uint32_t b0, uint32_t b1) {
    asm volatile(
        "mma.sync.aligned.m16n8k8.row.col.f32.tf32.tf32.f32 "
        "{%0,%1,%2,%3}, {%4,%5,%6,%7}, {%8,%9}, {%0,%1,%2,%3};"
        : "+f"(c[0]), "+f"(c[1]), "+f"(c[2]), "+f"(c[3])
        : "r"(a0), "r"(a1), "r"(a2), "r"(a3), "r"(b0), "r"(b1));
}
#define CP_ASYNC16(dst, src) \
    asm volatile("cp.async.cg.shared.global [%0], [%1], 16;" :: "r"(dst), "l"(src))
#define CP_COMMIT()  asm volatile("cp.async.commit_group;")
#define CP_WAIT_1()  asm volatile("cp.async.wait_group 1;")
#define CP_WAIT_0()  asm volatile("cp.async.wait_group 0;")

// ---------------------------------------------------------------------------
// Elementwise RNA-round-to-TF32 copy (pre-pass; n % 4 == 0)
// ---------------------------------------------------------------------------
__global__ void round_tf32(const float* __restrict__ in, float* __restrict__ out, int n)
{
    int i = (blockIdx.x * 256 + threadIdx.x) * 4;
    if (i < n) {
        float4 v = *(const float4*)(in + i);
        uint4 u = make_uint4(f2tf(v.x), f2tf(v.y), f2tf(v.z), f2tf(v.w));
        *(uint4*)(out + i) = u;
    }
}

// ---------------------------------------------------------------------------
// TF32 tensor-core GEMM, 3-stage cp.async pipeline, fused epilogues.
// ALL operands must be pre-rounded to TF32 (raw-bit fragment loads, no cvt).
// RND=true rounds the stored output to TF32 (for consumers' A operands).
// ---------------------------------------------------------------------------
enum { EPI_NONE = 0, EPI_BIAS = 1, EPI_BIAS_GELU = 2, EPI_BIAS_RES = 3 };

template <int BM, int BN>
struct GemmSmem {
    static constexpr int BK  = 16;
    static constexpr int STG = 3;
    static constexpr int APAD = 20;
    static constexpr int B_STRIDE = BN + 4;
    static constexpr int A_FLOATS = STG * BM * APAD;
    static constexpr int B_FLOATS = STG * BK * B_STRIDE;
    static constexpr int BYTES = (A_FLOATS + B_FLOATS) * 4;
};

template <int BM, int BN, int WARPS_M, int WARPS_N, int EPI, bool RND>
__global__ void __launch_bounds__(256)
mma_gemm(const float* __restrict__ A, int lda,
         const float* __restrict__ Bp, int ldb,
         float* __restrict__ C, int ldc,
         const float* __restrict__ bias,
         const float* __restrict__ res, int ldres,
         int K)
{
    static_assert(WARPS_M * WARPS_N == 8, "256 threads");
    using SM = GemmSmem<BM, BN>;
    constexpr int BK  = SM::BK;
    constexpr int STG = SM::STG;
    constexpr int WM  = BM / WARPS_M;
    constexpr int WN  = BN / WARPS_N;
    constexpr int MT  = WM / 16;
    constexpr int NT_ = WN / 8;
    constexpr int APAD = SM::APAD;
    constexpr int B_STRIDE = SM::B_STRIDE;

    extern __shared__ float dynsm[];
    float* Asf = dynsm;                              // [STG][BM][APAD]
    float* Bsf = dynsm + SM::A_FLOATS;               // [STG][BK][B_STRIDE]
#define AS(s, r, c) Asf[((s) * BM + (r)) * APAD + (c)]
#define BS(s, r, c) Bsf[((s) * BK + (r)) * B_STRIDE + (c)]

    const int tid  = threadIdx.x;
    const int warp = tid >> 5;
    const int lane = tid & 31;
    const int gid  = lane >> 2;
    const int tig  = lane & 3;
    const int wm   = (warp / WARPS_N) * WM;
    const int wn   = (warp % WARPS_N) * WN;

    const int rowBase = blockIdx.y * BM;
    const int colBase = blockIdx.x * BN;

    float acc[MT][NT_][4];
#pragma unroll
    for (int i = 0; i < MT; i++)
#pragma unroll
        for (int j = 0; j < NT_; j++)
#pragma unroll
            for (int r = 0; r < 4; r++) acc[i][j][r] = 0.0f;

    auto load_tile = [&](int st, int k0) {
        constexpr int AV = BM * 4;
#pragma unroll
        for (int i = tid; i < AV; i += 256) {
            int row = i >> 2, c = (i & 3) << 2;
            CP_ASYNC16(smem_u32(&AS(st, row, c)),
                       &A[(size_t)(rowBase + row) * lda + k0 + c]);
        }
        constexpr int BV = BK * (BN / 4);
#pragma unroll
        for (int i = tid; i < BV; i += 256) {
            int kk = i / (BN / 4), c = (i % (BN / 4)) << 2;
            CP_ASYNC16(smem_u32(&BS(st, kk, c)),
                       &Bp[(size_t)(k0 + kk) * ldb + colBase + c]);
        }
    };

    const int nTiles = K / BK;          // >= 3 for all call sites
    load_tile(0, 0);
    CP_COMMIT();
    load_tile(1, BK);
    CP_COMMIT();

    for (int t = 0; t < nTiles; t++) {
        const int st = t % STG;
        if (t + 1 < nTiles) CP_WAIT_1(); else CP_WAIT_0();
        __syncthreads();                 // tile t visible; buffer (t+2)%STG free
        if (t + 2 < nTiles) {
            load_tile((t + 2) % STG, (t + 2) * BK);
            CP_COMMIT();
        }

#pragma unroll
        for (int kb = 0; kb < BK; kb += 8) {
            uint32_t af[MT][4];
#pragma unroll
            for (int mt = 0; mt < MT; mt++) {
                const int m0 = wm + mt * 16;
                af[mt][0] = __float_as_uint(AS(st, m0 + gid,     kb + tig    ));
                af[mt][1] = __float_as_uint(AS(st, m0 + gid + 8, kb + tig    ));
                af[mt][2] = __float_as_uint(AS(st, m0 + gid,     kb + tig + 4));
                af[mt][3] = __float_as_uint(AS(st, m0 + gid + 8, kb + tig + 4));
            }
            uint32_t bf[NT_][2];
#pragma unroll
            for (int nt = 0; nt < NT_; nt++) {
                const int n0 = wn + nt * 8;
                bf[nt][0] = __float_as_uint(BS(st, kb + tig,     n0 + gid));
                bf[nt][1] = __float_as_uint(BS(st, kb + tig + 4, n0 + gid));
            }
#pragma unroll
            for (int mt = 0; mt < MT; mt++)
#pragma unroll
                for (int nt = 0; nt < NT_; nt++)
                    mma_tf32(acc[mt][nt], af[mt][0], af[mt][1], af[mt][2], af[mt][3],
                             bf[nt][0], bf[nt][1]);
        }
    }
#undef AS
#undef BS

#pragma unroll
    for (int mt = 0; mt < MT; mt++) {
        const int row0 = rowBase + wm + mt * 16 + gid;
        const int row1 = row0 + 8;
#pragma unroll
        for (int nt = 0; nt < NT_; nt++) {
            const int col = colBase + wn + nt * 8 + 2 * tig;
            float v0 = acc[mt][nt][0], v1 = acc[mt][nt][1];
            float v2 = acc[mt][nt][2], v3 = acc[mt][nt][3];
            if (EPI == EPI_BIAS || EPI == EPI_BIAS_GELU || EPI == EPI_BIAS_RES) {
                const float b0 = bias[col], b1 = bias[col + 1];
                v0 += b0; v1 += b1; v2 += b0; v3 += b1;
            }
            if (EPI == EPI_BIAS_GELU) {
                v0 = 0.5f * v0 * (1.0f + erff(v0 * 0.70710678118654752f));
                v1 = 0.5f * v1 * (1.0f + erff(v1 * 0.70710678118654752f));
                v2 = 0.5f * v2 * (1.0f + erff(v2 * 0.70710678118654752f));
                v3 = 0.5f * v3 * (1.0f + erff(v3 * 0.70710678118654752f));
            }
            if (EPI == EPI_BIAS_RES) {
                const float2 r0 = *(const float2*)&res[(size_t)row0 * ldres + col];
                const float2 r1 = *(const float2*)&res[(size_t)row1 * ldres + col];
                v0 += r0.x; v1 += r0.y; v2 += r1.x; v3 += r1.y;
            }
            if (RND) {
                v0 = f2tf_f(v0); v1 = f2tf_f(v1); v2 = f2tf_f(v2); v3 = f2tf_f(v3);
            }
            *(float2*)&C[(size_t)row0 * ldc + col] = make_float2(v0, v1);
            *(float2*)&C[(size_t)row1 * ldc + col] = make_float2(v2, v3);
        }
    }
}

// ---------------------------------------------------------------------------
// Fused flash attention (TF32 mma, online softmax, S never leaves the SM).
// Grid: (8 q-tiles, 96 bh). 256 threads = 8 warps; warp w owns S rows 16w..16w+15.
// qkv is PRE-ROUNDED to TF32 -> Q/K/V fragments are raw bit loads (no cvt).
// Only the P (softmax) fragments need cvt. Output rounded for the proj GEMM.
// ---------------------------------------------------------------------------
#define FA_PAD 68
#define FA_QOFF 0
#define FA_KOFF (128 * FA_PAD)
#define FA_VOFF (FA_KOFF + 2 * 128 * FA_PAD)
#define FA_SMEM ((FA_VOFF + 2 * 128 * FA_PAD) * 4)

__global__ void __launch_bounds__(256, 1)
flash_attn(const float* __restrict__ qkv, float* __restrict__ attn)
{
    extern __shared__ float sm[];
    float* Qs = sm + FA_QOFF;
    float* Ks = sm + FA_KOFF;   // [2][128][FA_PAD]
    float* Vs = sm + FA_VOFF;

    const int tid  = threadIdx.x;
    const int warp = tid >> 5;
    const int lane = tid & 31;
    const int gid  = lane >> 2;
    const int tig  = lane & 3;

    const int bh = blockIdx.y;
    const int b  = bh / NHEAD;
    const int h  = bh - b * NHEAD;
    const float* qp = qkv + (size_t)b * SEQ * TD + h * HD;
    const float* kp = qp + DIM;
    const float* vp = qp + 2 * DIM;
    const int q0 = blockIdx.x * 128;

    // ---- load Q tile + prefetch K0/V0 (one commit group)
#pragma unroll
    for (int i = tid; i < 128 * 16; i += 256) {
        int row = i >> 4, c = (i & 15) << 2;
        CP_ASYNC16(smem_u32(&Qs[row * FA_PAD + c]), &qp[(size_t)(q0 + row) * TD + c]);
    }
#pragma unroll
    for (int i = tid; i < 128 * 16; i += 256) {
        int row = i >> 4, c = (i & 15) << 2;
        CP_ASYNC16(smem_u32(&Ks[row * FA_PAD + c]), &kp[(size_t)row * TD + c]);
        CP_ASYNC16(smem_u32(&Vs[row * FA_PAD + c]), &vp[(size_t)row * TD + c]);
    }
    CP_COMMIT();

    uint32_t qf[8][4];                  // Q fragments, raw bits (pre-rounded)
    float oacc[8][4];
#pragma unroll
    for (int i = 0; i < 8; i++)
#pragma unroll
        for (int r = 0; r < 4; r++) oacc[i][r] = 0.0f;
    float m0 = -1e30f, m1 = -1e30f, l0 = 0.0f, l1 = 0.0f;

    const int r0s = 16 * warp + gid;    // smem row (lo)
    for (int t = 0; t < 8; t++) {
        const int st = t & 1;
        if (t < 7) {
            const int nb = (t + 1) & 1;
            const float* kn = kp + (size_t)(t + 1) * 128 * TD;
            const float* vn = vp + (size_t)(t + 1) * 128 * TD;
#pragma unroll
            for (int i = tid; i < 128 * 16; i += 256) {
                int row = i >> 4, c = (i & 15) << 2;
                CP_ASYNC16(smem_u32(&Ks[(nb * 128 + row) * FA_PAD + c]), &kn[(size_t)row * TD + c]);
                CP_ASYNC16(smem_u32(&Vs[(nb * 128 + row) * FA_PAD + c]), &vn[(size_t)row * TD + c]);
            }
            CP_COMMIT();
            CP_WAIT_1();
        } else {
            CP_WAIT_0();
        }
        __syncthreads();

        if (t == 0) {
#pragma unroll
            for (int kb = 0; kb < 8; kb++) {
                qf[kb][0] = __float_as_uint(Qs[(r0s    ) * FA_PAD + kb * 8 + tig    ]);
                qf[kb][1] = __float_as_uint(Qs[(r0s + 8) * FA_PAD + kb * 8 + tig    ]);
                qf[kb][2] = __float_as_uint(Qs[(r0s    ) * FA_PAD + kb * 8 + tig + 4]);
                qf[kb][3] = __float_as_uint(Qs[(r0s + 8) * FA_PAD + kb * 8 + tig + 4]);
            }
        }

        // ---- S = Q @ K^T  (16 rows x 128 cols per warp); raw-bit K frags
        float sacc[16][4];
#pragma unroll
        for (int i = 0; i < 16; i++)
#pragma unroll
            for (int r = 0; r < 4; r++) sacc[i][r] = 0.0f;

        const float* Kb = Ks + st * 128 * FA_PAD;
#pragma unroll
        for (int kb = 0; kb < 8; kb++) {
#pragma unroll
            for (int nt = 0; nt < 16; nt++) {
                uint32_t b0 = __float_as_uint(Kb[(nt * 8 + gid) * FA_PAD + kb * 8 + tig    ]);
                uint32_t b1 = __float_as_uint(Kb[(nt * 8 + gid) * FA_PAD + kb * 8 + tig + 4]);
                mma_tf32(sacc[nt], qf[kb][0], qf[kb][1], qf[kb][2], qf[kb][3], b0, b1);
            }
        }

        // ---- online softmax (rows gid / gid+8; stats live within the quad)
        float mx0 = -1e30f, mx1 = -1e30f;
#pragma unroll
        for (int nt = 0; nt < 16; nt++) {
            sacc[nt][0] *= 0.125f; sacc[nt][1] *= 0.125f;
            sacc[nt][2] *= 0.125f; sacc[nt][3] *= 0.125f;
            mx0 = fmaxf(mx0, fmaxf(sacc[nt][0], sacc[nt][1]));
            mx1 = fmaxf(mx1, fmaxf(sacc[nt][2], sacc[nt][3]));
        }
        mx0 = fmaxf(mx0, __shfl_xor_sync(0xffffffffu, mx0, 1));
        mx0 = fmaxf(mx0, __shfl_xor_sync(0xffffffffu, mx0, 2));
        mx1 = fmaxf(mx1, __shfl_xor_sync(0xffffffffu, mx1, 1));
        mx1 = fmaxf(mx1, __shfl_xor_sync(0xffffffffu, mx1, 2));

        const float mn0 = fmaxf(m0, mx0), mn1 = fmaxf(m1, mx1);
        const float f0 = __expf(m0 - mn0), f1 = __expf(m1 - mn1);
        m0 = mn0; m1 = mn1;
        l0 *= f0;  l1 *= f1;
#pragma unroll
        for (int nd = 0; nd < 8; nd++) {
            oacc[nd][0] *= f0; oacc[nd][1] *= f0;
            oacc[nd][2] *= f1; oacc[nd][3] *= f1;
        }
#pragma unroll
        for (int nt = 0; nt < 16; nt++) {
            sacc[nt][0] = __expf(sacc[nt][0] - m0);
            sacc[nt][1] = __expf(sacc[nt][1] - m0);
            sacc[nt][2] = __expf(sacc[nt][2] - m1);
            sacc[nt][3] = __expf(sacc[nt][3] - m1);
            l0 += sacc[nt][0] + sacc[nt][1];
            l1 += sacc[nt][2] + sacc[nt][3];
        }

        // ---- O += P @ V  (A-frags from sacc via width-4 shuffles; V raw bits)
        const float* Vb = Vs + st * 128 * FA_PAD;
        const int s1 = tig >> 1, s2 = s1 + 2;
        const bool odd = (tig & 1);
#pragma unroll
        for (int kk = 0; kk < 16; kk++) {
            float v00 = __shfl_sync(0xffffffffu, sacc[kk][0], s1, 4);
            float v01 = __shfl_sync(0xffffffffu, sacc[kk][1], s1, 4);
            float v02 = __shfl_sync(0xffffffffu, sacc[kk][0], s2, 4);
            float v03 = __shfl_sync(0xffffffffu, sacc[kk][1], s2, 4);
            float v10 = __shfl_sync(0xffffffffu, sacc[kk][2], s1, 4);
            float v11 = __shfl_sync(0xffffffffu, sacc[kk][3], s1, 4);
            float v12 = __shfl_sync(0xffffffffu, sacc[kk][2], s2, 4);
            float v13 = __shfl_sync(0xffffffffu, sacc[kk][3], s2, 4);
            uint32_t a0 = f2tf(odd ? v01 : v00);
            uint32_t a2 = f2tf(odd ? v03 : v02);
            uint32_t a1 = f2tf(odd ? v11 : v10);
            uint32_t a3 = f2tf(odd ? v13 : v12);
#pragma unroll
            for (int nd = 0; nd < 8; nd++) {
                uint32_t b0 = __float_as_uint(Vb[(kk * 8 + tig    ) * FA_PAD + nd * 8 + gid]);
                uint32_t b1 = __float_as_uint(Vb[(kk * 8 + tig + 4) * FA_PAD + nd * 8 + gid]);
                mma_tf32(oacc[nd], a0, a1, a2, a3, b0, b1);
            }
        }
        __syncthreads();
    }

    // ---- normalize, ROUND TO TF32, store (head-interleaved into attn [B,N,D])
    l0 += __shfl_xor_sync(0xffffffffu, l0, 1);
    l0 += __shfl_xor_sync(0xffffffffu, l0, 2);
    l1 += __shfl_xor_sync(0xffffffffu, l1, 1);
    l1 += __shfl_xor_sync(0xffffffffu, l1, 2);
    const float inv0 = 1.0f / l0, inv1 = 1.0f / l1;

    const size_t grow0 = (size_t)b * SEQ + q0 + 16 * warp + gid;
#pragma unroll
    for (int nd = 0; nd < 8; nd++) {
        const int col = h * HD + nd * 8 + 2 * tig;
        *(float2*)&attn[grow0 * DIM + col] =
            make_float2(f2tf_f(oacc[nd][0] * inv0), f2tf_f(oacc[nd][1] * inv0));
        *(float2*)&attn[(grow0 + 8) * DIM + col] =
            make_float2(f2tf_f(oacc[nd][2] * inv1), f2tf_f(oacc[nd][3] * inv1));
    }
}

// ---------------------------------------------------------------------------
// LayerNorm over 768 columns; optional second output rounded to TF32.
// ---------------------------------------------------------------------------
__global__ void layernorm_768(const float* __restrict__ in, float* __restrict__ out,
                              float* __restrict__ out_r,
                              const float* __restrict__ g, const float* __restrict__ bb)
{
    __shared__ float sm[33];
    const size_t row = blockIdx.x;
    const float* p = in + row * DIM;
    const int t = threadIdx.x;
    const float x0 = p[t], x1 = p[t + 256], x2 = p[t + 512];

    float s = x0 + x1 + x2;
#pragma unroll
    for (int o = 16; o; o >>= 1) s += __shfl_xor_sync(0xffffffffu, s, o);
    const int w = t >> 5, l = t & 31;
    if (l == 0) sm[w] = s;
    __syncthreads();
    if (t == 0) {
        float r = 0.0f;
#pragma unroll
        for (int i = 0; i < 8; i++) r += sm[i];
        sm[32] = r;
    }
    __syncthreads();
    const float mu = sm[32] * (1.0f / DIM);

    const float d0 = x0 - mu, d1 = x1 - mu, d2 = x2 - mu;
    float q = d0 * d0 + d1 * d1 + d2 * d2;
#pragma unroll
    for (int o = 16; o; o >>= 1) q += __shfl_xor_sync(0xffffffffu, q, o);
    __syncthreads();
    if (l == 0) sm[w] = q;
    __syncthreads();
    if (t == 0) {
        float r = 0.0f;
#pragma unroll
        for (int i = 0; i < 8; i++) r += sm[i];
        sm[32] = r;
    }
    __syncthreads();
    const float var = sm[32] * (1.0f / DIM);
    const float inv = rsqrtf(var + 1e-6f);

    const float o0 = d0 * inv * g[t]       + bb[t];
    const float o1 = d1 * inv * g[t + 256] + bb[t + 256];
    const float o2 = d2 * inv * g[t + 512] + bb[t + 512];
    float* o = out + row * DIM;
    o[t] = o0; o[t + 256] = o1; o[t + 512] = o2;
    if (out_r) {
        float* orr = out_r + row * DIM;
        orr[t]       = f2tf_f(o0);
        orr[t + 256] = f2tf_f(o1);
        orr[t + 512] = f2tf_f(o2);
    }
}

// ---------------------------------------------------------------------------
// Launch
// ---------------------------------------------------------------------------
extern "C" void kernel_launch(void* const* d_in, const int* in_sizes, int n_in,
                              void* d_out, int out_size)
{
    const float* x      = (const float*)d_in[0];
    const float* qkv_w  = (const float*)d_in[1];
    const float* qkv_b  = (const float*)d_in[2];
    const float* proj_w = (const float*)d_in[3];
    const float* proj_b = (const float*)d_in[4];
    const float* ln1_g  = (const float*)d_in[5];
    const float* ln1_b  = (const float*)d_in[6];
    const float* ln2_g  = (const float*)d_in[7];
    const float* ln2_b  = (const float*)d_in[8];
    const float* fc1_w  = (const float*)d_in[9];
    const float* fc1_b  = (const float*)d_in[10];
    const float* fc2_w  = (const float*)d_in[11];
    const float* fc2_b  = (const float*)d_in[12];
    float* out = (float*)d_out;

    float *qkv, *attn, *x1, *x1r, *y, *h, *xr, *wr;
    cudaGetSymbolAddress((void**)&qkv,  g_qkv);
    cudaGetSymbolAddress((void**)&attn, g_attn);
    cudaGetSymbolAddress((void**)&x1,   g_x1);
    cudaGetSymbolAddress((void**)&x1r,  g_x1r);
    cudaGetSymbolAddress((void**)&y,    g_y);
    cudaGetSymbolAddress((void**)&h,    g_h);
    cudaGetSymbolAddress((void**)&xr,   g_xr);
    cudaGetSymbolAddress((void**)&wr,   g_wr);

    // Host-side attribute sets: immediate, idempotent, capture-safe.
    constexpr int GS = GemmSmem<128,128>::BYTES;
    cudaFuncSetAttribute(mma_gemm<128,128,2,4,EPI_BIAS,true>,
                         cudaFuncAttributeMaxDynamicSharedMemorySize, GS);
    cudaFuncSetAttribute(mma_gemm<128,128,2,4,EPI_BIAS_RES,false>,
                         cudaFuncAttributeMaxDynamicSharedMemorySize, GS);
    cudaFuncSetAttribute(mma_gemm<128,128,2,4,EPI_BIAS_GELU,true>,
                         cudaFuncAttributeMaxDynamicSharedMemorySize, GS);
    cudaFuncSetAttribute(flash_attn, cudaFuncAttributeMaxDynamicSharedMemorySize, FA_SMEM);

    // 0) Pre-round weights + x to TF32 (RNA), into scratch
    round_tf32<<<(DIM*TD   + 1023)/1024, 256>>>(qkv_w,  wr + WOFF_QKV,  DIM*TD);
    round_tf32<<<(DIM*DIM  + 1023)/1024, 256>>>(proj_w, wr + WOFF_PROJ, DIM*DIM);
    round_tf32<<<(DIM*HMLP + 1023)/1024, 256>>>(fc1_w,  wr + WOFF_FC1,  DIM*HMLP);
    round_tf32<<<(HMLP*DIM + 1023)/1024, 256>>>(fc2_w,  wr + WOFF_FC2,  HMLP*DIM);
    round_tf32<<<(ROWS*DIM + 1023)/1024, 256>>>(x, xr, ROWS*DIM);

    // 1) QKV projection: xr @ qkv_wr + b -> g_qkv (rounded for flash)
    mma_gemm<128,128,2,4,EPI_BIAS,true><<<dim3(TD/128, ROWS/128), 256, GS>>>(
        xr, DIM, wr + WOFF_QKV, TD, qkv, TD, qkv_b, nullptr, 0, DIM);

    // 2-4) Fused flash attention -> g_attn (rounded for proj)
    flash_attn<<<dim3(SEQ/128, B_*NHEAD), 256, FA_SMEM>>>(qkv, attn);

    // 5) Proj + bias + residual(x full fp32) -> g_y
    mma_gemm<128,128,2,4,EPI_BIAS_RES,false><<<dim3(DIM/128, ROWS/128), 256, GS>>>(
        attn, DIM, wr + WOFF_PROJ, DIM, y, DIM, proj_b, x, DIM, DIM);

    // 6) LN1 -> x1 (full, FC2 residual) + x1r (rounded, FC1 operand)
    layernorm_768<<<ROWS, 256>>>(y, x1, x1r, ln1_g, ln1_b);

    // 7) FC1 + bias + exact GELU -> g_h (rounded for FC2)
    mma_gemm<128,128,2,4,EPI_BIAS_GELU,true><<<dim3(HMLP/128, ROWS/128), 256, GS>>>(
        x1r, DIM, wr + WOFF_FC1, HMLP, h, HMLP, fc1_b, nullptr, 0, DIM);

    // 8) FC2 + bias + residual(x1 full) -> g_y
    mma_gemm<128,128,2,4,EPI_BIAS_RES,false><<<dim3(DIM/128, ROWS/128), 256, GS>>>(
        h, HMLP, wr + WOFF_FC2, DIM, y, DIM, fc2_b, x1, DIM, HMLP);

    // 9) LN2 -> out (full precision, no rounded copy)
    layernorm_768<<<ROWS, 256>>>(y, out, nullptr, ln2_g, ln2_b);
}